// round 13
// baseline (speedup 1.0000x reference)
#include <cuda_runtime.h>
#include <cuda_fp16.h>
#include <math.h>
#include <stdint.h>

#define EDIM   1024
#define BDIM   8192
#define TM     128
#define TN     256
#define BK     32                  // f16 elems per stage per row (64 bytes)
#define NCHUNK (EDIM / BK)         // 32
#define STAGES 4

#define A_STAGE_BYTES (TM * BK * 2)                      // 8192
#define B_STAGE_BYTES (TN * BK * 2)                      // 16384
#define B_BASE_OFF    (STAGES * A_STAGE_BYTES)           // 32768
#define SMEM_DYN      (STAGES * (A_STAGE_BYTES + B_STAGE_BYTES))  // 98304

// ---------------- static device scratch (no runtime alloc) ----------------
__device__ __align__(256) __half g_A16[(size_t)BDIM * EDIM];
__device__ __align__(256) __half g_P16[(size_t)BDIM * EDIM];
__device__ float              g_ap[BDIM];
__device__ float              g_rna[BDIM];
__device__ float              g_rnp[BDIM];
__device__ unsigned long long g_neg[BDIM];   // (fenc(val)<<32) | col_idx

// Order-preserving float -> uint encoding (for packed 64-bit atomicMin)
__device__ __forceinline__ unsigned fenc(float f) {
    unsigned u = __float_as_uint(f);
    return (u & 0x80000000u) ? ~u : (u | 0x80000000u);
}

// bit-cast __half2 -> uint32_t
__device__ __forceinline__ uint32_t h2_as_u32(__half2 h) {
    return *reinterpret_cast<uint32_t*>(&h);
}

#define CP_ASYNC16(dst, src) \
    asm volatile("cp.async.cg.shared.global [%0], [%1], 16;" :: "r"(dst), "l"(src))
#define CP_COMMIT() asm volatile("cp.async.commit_group;" ::: "memory")
#define CP_WAIT(n)  asm volatile("cp.async.wait_group %0;" :: "n"(n) : "memory")

__device__ __forceinline__ void ldsm_x4(uint32_t& r0, uint32_t& r1,
                                        uint32_t& r2, uint32_t& r3, uint32_t a) {
    asm volatile("ldmatrix.sync.aligned.m8n8.x4.shared.b16 {%0,%1,%2,%3}, [%4];"
                 : "=r"(r0), "=r"(r1), "=r"(r2), "=r"(r3) : "r"(a));
}

// f16 in, f16 accumulate (2 packed half2 regs for C/D)
__device__ __forceinline__ void mma_f16acc(uint32_t& c0, uint32_t& c1,
                                           uint32_t a0, uint32_t a1, uint32_t a2, uint32_t a3,
                                           uint32_t b0, uint32_t b1) {
    asm volatile(
        "mma.sync.aligned.m16n8k16.row.col.f16.f16.f16.f16 "
        "{%0,%1}, {%2,%3,%4,%5}, {%6,%7}, {%0,%1};"
        : "+r"(c0), "+r"(c1)
        : "r"(a0), "r"(a1), "r"(a2), "r"(a3), "r"(b0), "r"(b1));
}

// Swizzled byte offset within a [rows][64B] tile (64B rows, 16B chunks)
__device__ __forceinline__ uint32_t sw_off(int r, int c) {
    return (uint32_t)(r * 64 + ((c ^ ((r >> 1) & 3)) << 4));
}

// ---------------------------------------------------------------------------
// Kernel 1: one WARP per row, barrier-free, fully streaming two-pass.
// Pass 1: accumulate sums only (no retention). Pass 2: re-read (L2-hot),
// convert, store. Reg budget pinned via __launch_bounds__ occupancy target.
// ---------------------------------------------------------------------------
__global__ __launch_bounds__(256, 6) void normalize_kernel(
    const float* __restrict__ A, const float* __restrict__ P,
    float* __restrict__ out)
{
    const int wid  = threadIdx.x >> 5;
    const int lane = threadIdx.x & 31;
    const int r    = blockIdx.x * 8 + wid;

    const float4* Ar = reinterpret_cast<const float4*>(A + (size_t)r * EDIM);
    const float4* Pr = reinterpret_cast<const float4*>(P + (size_t)r * EDIM);

    // Pass 1: streaming sums (MLP=16 via unroll, nothing retained)
    float sa = 0.f, sp = 0.f, sap = 0.f;
    #pragma unroll
    for (int i = 0; i < 8; ++i) {
        const float4 a = Ar[lane + 32 * i];
        const float4 p = Pr[lane + 32 * i];
        sa  += a.x*a.x + a.y*a.y + a.z*a.z + a.w*a.w;
        sp  += p.x*p.x + p.y*p.y + p.z*p.z + p.w*p.w;
        sap += a.x*p.x + a.y*p.y + a.z*p.z + a.w*p.w;
    }

    #pragma unroll
    for (int o = 16; o > 0; o >>= 1) {
        sa  += __shfl_xor_sync(0xffffffffu, sa,  o);
        sp  += __shfl_xor_sync(0xffffffffu, sp,  o);
        sap += __shfl_xor_sync(0xffffffffu, sap, o);
    }

    const float rna = rsqrtf(sa), rnp = rsqrtf(sp);

    if (lane == 0) {
        g_ap[r]  = sap / fmaxf(sqrtf(sa) * sqrtf(sp), 1e-8f);
        g_rna[r] = rna;
        g_rnp[r] = rnp;
        g_neg[r] = 0xFFFFFFFFFFFFFFFFull;
        if (r == 0) out[0] = 0.0f;
    }

    // Pass 2: re-read (L2-hit), convert to f16, store.
    uint2* da = reinterpret_cast<uint2*>(g_A16 + (size_t)r * EDIM);
    uint2* dp = reinterpret_cast<uint2*>(g_P16 + (size_t)r * EDIM);
    #pragma unroll
    for (int i = 0; i < 8; ++i) {
        const int f = lane + 32 * i;
        const float4 a = Ar[f];
        const float4 p = Pr[f];
        __half2 a0 = __floats2half2_rn(a.x * rna, a.y * rna);
        __half2 a1 = __floats2half2_rn(a.z * rna, a.w * rna);
        __half2 p0 = __floats2half2_rn(p.x * rnp, p.y * rnp);
        __half2 p1 = __floats2half2_rn(p.z * rnp, p.w * rnp);
        da[f] = make_uint2(h2_as_u32(a0), h2_as_u32(a1));
        dp[f] = make_uint2(h2_as_u32(p0), h2_as_u32(p1));
    }
}

// ---------------------------------------------------------------------------
// Kernel 2 (CHAMPION, unchanged): f16 mma.sync (f16 accum) GEMM with fused
// per-row argmin epilogue. 128x256 CTA tile, BK=32, 4-stage cp.async
// pipeline, 8 warps, 2 CTAs/SM, single barrier per chunk.
// ---------------------------------------------------------------------------
__device__ __forceinline__ void load_stage(uint32_t sbase, int slot, int chunk,
                                           int row0, int col0, int tid)
{
    const size_t k0b = (size_t)chunk * (BK * 2);
    const char* Ab = (const char*)g_A16;
    const char* Bb = (const char*)g_P16;

    const uint32_t ad0 = sbase + slot * A_STAGE_BYTES;
    #pragma unroll
    for (int i = 0; i < 2; ++i) {                   // 512 chunks of 16B
        int u = i * 256 + tid;
        int r = u >> 2, c = u & 3;
        CP_ASYNC16(ad0 + sw_off(r, c),
                   Ab + (size_t)(row0 + r) * (EDIM * 2) + k0b + c * 16);
    }
    const uint32_t bd0 = sbase + B_BASE_OFF + slot * B_STAGE_BYTES;
    #pragma unroll
    for (int i = 0; i < 4; ++i) {                   // 1024 chunks of 16B
        int u = i * 256 + tid;
        int r = u >> 2, c = u & 3;
        CP_ASYNC16(bd0 + sw_off(r, c),
                   Bb + (size_t)(col0 + r) * (EDIM * 2) + k0b + c * 16);
    }
}

__global__ __launch_bounds__(256, 2) void gemm_min_f16()
{
    extern __shared__ char dynsmem[];
    const uint32_t sbase = (uint32_t)__cvta_generic_to_shared(dynsmem);

    const int tid   = threadIdx.x;
    const int wid   = tid >> 5;
    const int lane  = tid & 31;
    const int wm    = wid >> 2;          // 0..1
    const int wn    = wid & 3;           // 0..3
    const int row0  = blockIdx.y * TM;
    const int col0  = blockIdx.x * TN;

    const int mi = lane >> 3;
    const int lr = lane & 7;

    // f16 accumulators: [mt][nf][g] g=0 rows 0-7, g=1 rows 8-15 (packed half2)
    uint32_t acc[4][8][2];
    #pragma unroll
    for (int mt = 0; mt < 4; ++mt)
        #pragma unroll
        for (int nf = 0; nf < 8; ++nf) { acc[mt][nf][0] = 0u; acc[mt][nf][1] = 0u; }

    #pragma unroll
    for (int s = 0; s < STAGES - 1; ++s) {
        load_stage(sbase, s, s, row0, col0, tid);
        CP_COMMIT();
    }

    for (int c = 0; c < NCHUNK; ++c) {
        const int s = c & (STAGES - 1);

        if      (c <= NCHUNK - 3) CP_WAIT(2);
        else if (c == NCHUNK - 2) CP_WAIT(1);
        else                      CP_WAIT(0);
        __syncthreads();   // orders cp.async visibility AND slot-reuse (WAR)

        if (c + STAGES - 1 < NCHUNK) {
            load_stage(sbase, (c + STAGES - 1) & (STAGES - 1),
                       c + STAGES - 1, row0, col0, tid);
            CP_COMMIT();
        }

        const uint32_t aS = sbase + s * A_STAGE_BYTES;
        const uint32_t bS = sbase + B_BASE_OFF + s * B_STAGE_BYTES;

        #pragma unroll
        for (int h = 0; h < 2; ++h) {          // two k16 halves of BK=32
            uint32_t af[4][4];
            uint32_t bf[8][2];
            #pragma unroll
            for (int mt = 0; mt < 4; ++mt) {
                const int r = wm * 64 + mt * 16 + (mi & 1) * 8 + lr;
                const int ch = 2 * h + (mi >> 1);
                ldsm_x4(af[mt][0], af[mt][1], af[mt][2], af[mt][3],
                        aS + sw_off(r, ch));
            }
            #pragma unroll
            for (int nt = 0; nt < 4; ++nt) {
                const int r = wn * 64 + nt * 16 + (mi & 1) * 8 + lr;
                const int ch = 2 * h + (mi >> 1);
                uint32_t r0, r1, r2, r3;
                ldsm_x4(r0, r1, r2, r3, bS + sw_off(r, ch));
                bf[2*nt][0]   = r0; bf[2*nt][1]   = r2;
                bf[2*nt+1][0] = r1; bf[2*nt+1][1] = r3;
            }
            #pragma unroll
            for (int mt = 0; mt < 4; ++mt)
                #pragma unroll
                for (int nf = 0; nf < 8; ++nf)
                    mma_f16acc(acc[mt][nf][0], acc[mt][nf][1],
                               af[mt][0], af[mt][1], af[mt][2], af[mt][3],
                               bf[nf][0], bf[nf][1]);
        }
        // no bottom barrier: next iteration's top sync covers slot reuse
    }

    // Epilogue: per-row (min value, col index) packed argmin, excl. diagonal.
    #pragma unroll
    for (int mt = 0; mt < 4; ++mt) {
        const int r_lo = row0 + wm * 64 + mt * 16 + (lane >> 2);
        const int r_hi = r_lo + 8;
        unsigned long long plo = 0xFFFFFFFFFFFFFFFFull;
        unsigned long long phi = 0xFFFFFFFFFFFFFFFFull;
        #pragma unroll
        for (int nf = 0; nf < 8; ++nf) {
            const __half2 vlo2 = *reinterpret_cast<const __half2*>(&acc[mt][nf][0]);
            const __half2 vhi2 = *reinterpret_cast<const __half2*>(&acc[mt][nf][1]);
            const float vl[2] = { __low2float(vlo2), __high2float(vlo2) };
            const float vh[2] = { __low2float(vhi2), __high2float(vhi2) };
            #pragma unroll
            for (int e = 0; e < 2; ++e) {
                const int gj = col0 + wn * 64 + nf * 8 + (lane & 3) * 2 + e;
                const unsigned long long klo =
                    ((unsigned long long)fenc(vl[e]) << 32) | (unsigned)gj;
                const unsigned long long khi =
                    ((unsigned long long)fenc(vh[e]) << 32) | (unsigned)gj;
                if (gj != r_lo && klo < plo) plo = klo;
                if (gj != r_hi && khi < phi) phi = khi;
            }
        }
        #pragma unroll
        for (int o = 1; o <= 2; o <<= 1) {
            unsigned long long t;
            t = __shfl_xor_sync(0xffffffffu, plo, o); if (t < plo) plo = t;
            t = __shfl_xor_sync(0xffffffffu, phi, o); if (t < phi) phi = t;
        }
        if ((lane & 3) == 0) {
            atomicMin(&g_neg[r_lo], plo);
            atomicMin(&g_neg[r_hi], phi);
        }
    }
}

// ---------------------------------------------------------------------------
// Kernel 3: one WARP per row, barrier-free exact fp32 recompute of an for the
// selected column; fused mean via atomicAdd.
// ---------------------------------------------------------------------------
__global__ __launch_bounds__(256) void an_term_kernel(
    const float* __restrict__ A, const float* __restrict__ P,
    float* __restrict__ out, int B)
{
    const int wid  = threadIdx.x >> 5;
    const int lane = threadIdx.x & 31;
    const int r    = blockIdx.x * 8 + wid;
    const int j    = (int)(unsigned)(g_neg[r] & 0xFFFFFFFFull);

    const float4* Ar = reinterpret_cast<const float4*>(A + (size_t)r * EDIM);
    const float4* Pj = reinterpret_cast<const float4*>(P + (size_t)j * EDIM);

    float s = 0.f;
    #pragma unroll
    for (int i = 0; i < 8; ++i) {
        const float4 a = Ar[lane + 32 * i];
        const float4 p = Pj[lane + 32 * i];
        s += a.x*p.x + a.y*p.y + a.z*p.z + a.w*p.w;
    }

    #pragma unroll
    for (int o = 16; o > 0; o >>= 1) s += __shfl_xor_sync(0xffffffffu, s, o);

    if (lane == 0) {
        const float an = s * g_rna[r] * g_rnp[j];
        const float term = fmaxf(1.0f + g_ap[r] - an, 0.f);
        atomicAdd(out, term * (1.0f / (float)B));
    }
}

extern "C" void kernel_launch(void* const* d_in, const int* in_sizes, int n_in,
                              void* d_out, int out_size)
{
    const float* anchor   = (const float*)d_in[0];
    const float* positive = (const float*)d_in[1];
    float* out = (float*)d_out;

    const int B = in_sizes[0] / EDIM;   // 8192

    cudaFuncSetAttribute(gemm_min_f16,
                         cudaFuncAttributeMaxDynamicSharedMemorySize, SMEM_DYN);

    normalize_kernel<<<B / 8, 256>>>(anchor, positive, out);
    dim3 grid(B / TN, B / TM);
    gemm_min_f16<<<grid, 256, SMEM_DYN>>>();
    an_term_kernel<<<B / 8, 256>>>(anchor, positive, out, B);
}

// round 14
// speedup vs baseline: 1.0650x; 1.0650x over previous
#include <cuda_runtime.h>
#include <cuda_fp16.h>
#include <math.h>
#include <stdint.h>

#define EDIM   1024
#define BDIM   8192
#define TM     128
#define TN     256
#define BK     32                  // f16 elems per stage per row (64 bytes)
#define NCHUNK (EDIM / BK)         // 32
#define STAGES 4

#define A_STAGE_BYTES (TM * BK * 2)                      // 8192
#define B_STAGE_BYTES (TN * BK * 2)                      // 16384
#define B_BASE_OFF    (STAGES * A_STAGE_BYTES)           // 32768
#define SMEM_DYN      (STAGES * (A_STAGE_BYTES + B_STAGE_BYTES))  // 98304

// ---------------- static device scratch (no runtime alloc) ----------------
__device__ __align__(256) __half g_A16[(size_t)BDIM * EDIM];
__device__ __align__(256) __half g_P16[(size_t)BDIM * EDIM];
__device__ float              g_ap[BDIM];
__device__ float              g_rna[BDIM];
__device__ float              g_rnp[BDIM];
__device__ unsigned long long g_neg[BDIM];   // (fenc(val)<<32) | col_idx

// Order-preserving float -> uint encoding (for packed 64-bit atomicMin)
__device__ __forceinline__ unsigned fenc(float f) {
    unsigned u = __float_as_uint(f);
    return (u & 0x80000000u) ? ~u : (u | 0x80000000u);
}

// bit-cast __half2 -> uint32_t
__device__ __forceinline__ uint32_t h2_as_u32(__half2 h) {
    return *reinterpret_cast<uint32_t*>(&h);
}

#define CP_ASYNC16(dst, src) \
    asm volatile("cp.async.cg.shared.global [%0], [%1], 16;" :: "r"(dst), "l"(src))
#define CP_COMMIT() asm volatile("cp.async.commit_group;" ::: "memory")
#define CP_WAIT(n)  asm volatile("cp.async.wait_group %0;" :: "n"(n) : "memory")

__device__ __forceinline__ void ldsm_x4(uint32_t& r0, uint32_t& r1,
                                        uint32_t& r2, uint32_t& r3, uint32_t a) {
    asm volatile("ldmatrix.sync.aligned.m8n8.x4.shared.b16 {%0,%1,%2,%3}, [%4];"
                 : "=r"(r0), "=r"(r1), "=r"(r2), "=r"(r3) : "r"(a));
}

// f16 in, f16 accumulate (2 packed half2 regs for C/D)
__device__ __forceinline__ void mma_f16acc(uint32_t& c0, uint32_t& c1,
                                           uint32_t a0, uint32_t a1, uint32_t a2, uint32_t a3,
                                           uint32_t b0, uint32_t b1) {
    asm volatile(
        "mma.sync.aligned.m16n8k16.row.col.f16.f16.f16.f16 "
        "{%0,%1}, {%2,%3,%4,%5}, {%6,%7}, {%0,%1};"
        : "+r"(c0), "+r"(c1)
        : "r"(a0), "r"(a1), "r"(a2), "r"(a3), "r"(b0), "r"(b1));
}

// Swizzled byte offset within a [rows][64B] tile (64B rows, 16B chunks)
__device__ __forceinline__ uint32_t sw_off(int r, int c) {
    return (uint32_t)(r * 64 + ((c ^ ((r >> 1) & 3)) << 4));
}

// ---------------------------------------------------------------------------
// Kernel 1: one WARP per row, barrier-free. Retains only A in registers;
// P is re-read in the store phase (register-resident reuse form — the
// L2-reuse variant was proven 2x slower in R13 by self-eviction).
// ---------------------------------------------------------------------------
__global__ __launch_bounds__(256) void normalize_kernel(
    const float* __restrict__ A, const float* __restrict__ P,
    float* __restrict__ out)
{
    const int wid  = threadIdx.x >> 5;
    const int lane = threadIdx.x & 31;
    const int r    = blockIdx.x * 8 + wid;

    const float4* Ar = reinterpret_cast<const float4*>(A + (size_t)r * EDIM);
    const float4* Pr = reinterpret_cast<const float4*>(P + (size_t)r * EDIM);

    // Phase 1: retain A; stream P through once for sums.
    float4 av[8];
    float sa = 0.f, sp = 0.f, sap = 0.f;
    #pragma unroll
    for (int i = 0; i < 8; ++i) av[i] = Ar[lane + 32 * i];
    #pragma unroll
    for (int i = 0; i < 8; ++i) {
        const float4 p = Pr[lane + 32 * i];
        sa  += av[i].x*av[i].x + av[i].y*av[i].y + av[i].z*av[i].z + av[i].w*av[i].w;
        sp  += p.x*p.x + p.y*p.y + p.z*p.z + p.w*p.w;
        sap += av[i].x*p.x + av[i].y*p.y + av[i].z*p.z + av[i].w*p.w;
    }

    #pragma unroll
    for (int o = 16; o > 0; o >>= 1) {
        sa  += __shfl_xor_sync(0xffffffffu, sa,  o);
        sp  += __shfl_xor_sync(0xffffffffu, sp,  o);
        sap += __shfl_xor_sync(0xffffffffu, sap, o);
    }

    const float rna = rsqrtf(sa), rnp = rsqrtf(sp);

    if (lane == 0) {
        g_ap[r]  = sap / fmaxf(sqrtf(sa) * sqrtf(sp), 1e-8f);
        g_rna[r] = rna;
        g_rnp[r] = rnp;
        g_neg[r] = 0xFFFFFFFFFFFFFFFFull;
        if (r == 0) out[0] = 0.0f;
    }

    // Phase 2: store A from registers; reload P and store.
    uint2* da = reinterpret_cast<uint2*>(g_A16 + (size_t)r * EDIM);
    uint2* dp = reinterpret_cast<uint2*>(g_P16 + (size_t)r * EDIM);
    #pragma unroll
    for (int i = 0; i < 8; ++i) {
        const int f = lane + 32 * i;
        __half2 a0 = __floats2half2_rn(av[i].x * rna, av[i].y * rna);
        __half2 a1 = __floats2half2_rn(av[i].z * rna, av[i].w * rna);
        da[f] = make_uint2(h2_as_u32(a0), h2_as_u32(a1));
        const float4 p = Pr[f];
        __half2 p0 = __floats2half2_rn(p.x * rnp, p.y * rnp);
        __half2 p1 = __floats2half2_rn(p.z * rnp, p.w * rnp);
        dp[f] = make_uint2(h2_as_u32(p0), h2_as_u32(p1));
    }
}

// ---------------------------------------------------------------------------
// Kernel 2 (CHAMPION): f16 mma.sync (f16 accum) GEMM with fused per-row
// argmin epilogue. 128x256 CTA tile, BK=32, 4-stage cp.async pipeline,
// 8 warps, 2 CTAs/SM, single barrier per chunk.
// ---------------------------------------------------------------------------
__device__ __forceinline__ void load_stage(uint32_t sbase, int slot, int chunk,
                                           int row0, int col0, int tid)
{
    const size_t k0b = (size_t)chunk * (BK * 2);
    const char* Ab = (const char*)g_A16;
    const char* Bb = (const char*)g_P16;

    const uint32_t ad0 = sbase + slot * A_STAGE_BYTES;
    #pragma unroll
    for (int i = 0; i < 2; ++i) {                   // 512 chunks of 16B
        int u = i * 256 + tid;
        int r = u >> 2, c = u & 3;
        CP_ASYNC16(ad0 + sw_off(r, c),
                   Ab + (size_t)(row0 + r) * (EDIM * 2) + k0b + c * 16);
    }
    const uint32_t bd0 = sbase + B_BASE_OFF + slot * B_STAGE_BYTES;
    #pragma unroll
    for (int i = 0; i < 4; ++i) {                   // 1024 chunks of 16B
        int u = i * 256 + tid;
        int r = u >> 2, c = u & 3;
        CP_ASYNC16(bd0 + sw_off(r, c),
                   Bb + (size_t)(col0 + r) * (EDIM * 2) + k0b + c * 16);
    }
}

__global__ __launch_bounds__(256, 2) void gemm_min_f16()
{
    extern __shared__ char dynsmem[];
    const uint32_t sbase = (uint32_t)__cvta_generic_to_shared(dynsmem);

    const int tid   = threadIdx.x;
    const int wid   = tid >> 5;
    const int lane  = tid & 31;
    const int wm    = wid >> 2;          // 0..1
    const int wn    = wid & 3;           // 0..3
    const int row0  = blockIdx.y * TM;
    const int col0  = blockIdx.x * TN;

    const int mi = lane >> 3;
    const int lr = lane & 7;

    // f16 accumulators: [mt][nf][g] g=0 rows 0-7, g=1 rows 8-15 (packed half2)
    uint32_t acc[4][8][2];
    #pragma unroll
    for (int mt = 0; mt < 4; ++mt)
        #pragma unroll
        for (int nf = 0; nf < 8; ++nf) { acc[mt][nf][0] = 0u; acc[mt][nf][1] = 0u; }

    #pragma unroll
    for (int s = 0; s < STAGES - 1; ++s) {
        load_stage(sbase, s, s, row0, col0, tid);
        CP_COMMIT();
    }

    for (int c = 0; c < NCHUNK; ++c) {
        const int s = c & (STAGES - 1);

        if      (c <= NCHUNK - 3) CP_WAIT(2);
        else if (c == NCHUNK - 2) CP_WAIT(1);
        else                      CP_WAIT(0);
        __syncthreads();   // orders cp.async visibility AND slot-reuse (WAR)

        if (c + STAGES - 1 < NCHUNK) {
            load_stage(sbase, (c + STAGES - 1) & (STAGES - 1),
                       c + STAGES - 1, row0, col0, tid);
            CP_COMMIT();
        }

        const uint32_t aS = sbase + s * A_STAGE_BYTES;
        const uint32_t bS = sbase + B_BASE_OFF + s * B_STAGE_BYTES;

        #pragma unroll
        for (int h = 0; h < 2; ++h) {          // two k16 halves of BK=32
            uint32_t af[4][4];
            uint32_t bf[8][2];
            #pragma unroll
            for (int mt = 0; mt < 4; ++mt) {
                const int r = wm * 64 + mt * 16 + (mi & 1) * 8 + lr;
                const int ch = 2 * h + (mi >> 1);
                ldsm_x4(af[mt][0], af[mt][1], af[mt][2], af[mt][3],
                        aS + sw_off(r, ch));
            }
            #pragma unroll
            for (int nt = 0; nt < 4; ++nt) {
                const int r = wn * 64 + nt * 16 + (mi & 1) * 8 + lr;
                const int ch = 2 * h + (mi >> 1);
                uint32_t r0, r1, r2, r3;
                ldsm_x4(r0, r1, r2, r3, bS + sw_off(r, ch));
                bf[2*nt][0]   = r0; bf[2*nt][1]   = r2;
                bf[2*nt+1][0] = r1; bf[2*nt+1][1] = r3;
            }
            #pragma unroll
            for (int mt = 0; mt < 4; ++mt)
                #pragma unroll
                for (int nf = 0; nf < 8; ++nf)
                    mma_f16acc(acc[mt][nf][0], acc[mt][nf][1],
                               af[mt][0], af[mt][1], af[mt][2], af[mt][3],
                               bf[nf][0], bf[nf][1]);
        }
        // no bottom barrier: next iteration's top sync covers slot reuse
    }

    // Epilogue: per-row (min value, col index) packed argmin, excl. diagonal.
    #pragma unroll
    for (int mt = 0; mt < 4; ++mt) {
        const int r_lo = row0 + wm * 64 + mt * 16 + (lane >> 2);
        const int r_hi = r_lo + 8;
        unsigned long long plo = 0xFFFFFFFFFFFFFFFFull;
        unsigned long long phi = 0xFFFFFFFFFFFFFFFFull;
        #pragma unroll
        for (int nf = 0; nf < 8; ++nf) {
            const __half2 vlo2 = *reinterpret_cast<const __half2*>(&acc[mt][nf][0]);
            const __half2 vhi2 = *reinterpret_cast<const __half2*>(&acc[mt][nf][1]);
            const float vl[2] = { __low2float(vlo2), __high2float(vlo2) };
            const float vh[2] = { __low2float(vhi2), __high2float(vhi2) };
            #pragma unroll
            for (int e = 0; e < 2; ++e) {
                const int gj = col0 + wn * 64 + nf * 8 + (lane & 3) * 2 + e;
                const unsigned long long klo =
                    ((unsigned long long)fenc(vl[e]) << 32) | (unsigned)gj;
                const unsigned long long khi =
                    ((unsigned long long)fenc(vh[e]) << 32) | (unsigned)gj;
                if (gj != r_lo && klo < plo) plo = klo;
                if (gj != r_hi && khi < phi) phi = khi;
            }
        }
        #pragma unroll
        for (int o = 1; o <= 2; o <<= 1) {
            unsigned long long t;
            t = __shfl_xor_sync(0xffffffffu, plo, o); if (t < plo) plo = t;
            t = __shfl_xor_sync(0xffffffffu, phi, o); if (t < phi) phi = t;
        }
        if ((lane & 3) == 0) {
            atomicMin(&g_neg[r_lo], plo);
            atomicMin(&g_neg[r_hi], phi);
        }
    }
}

// ---------------------------------------------------------------------------
// Kernel 3: one WARP per row, barrier-free exact fp32 recompute of an for the
// selected column; fused mean via atomicAdd.
// ---------------------------------------------------------------------------
__global__ __launch_bounds__(256) void an_term_kernel(
    const float* __restrict__ A, const float* __restrict__ P,
    float* __restrict__ out, int B)
{
    const int wid  = threadIdx.x >> 5;
    const int lane = threadIdx.x & 31;
    const int r    = blockIdx.x * 8 + wid;
    const int j    = (int)(unsigned)(g_neg[r] & 0xFFFFFFFFull);

    const float4* Ar = reinterpret_cast<const float4*>(A + (size_t)r * EDIM);
    const float4* Pj = reinterpret_cast<const float4*>(P + (size_t)j * EDIM);

    float s = 0.f;
    #pragma unroll
    for (int i = 0; i < 8; ++i) {
        const float4 a = Ar[lane + 32 * i];
        const float4 p = Pj[lane + 32 * i];
        s += a.x*p.x + a.y*p.y + a.z*p.z + a.w*p.w;
    }

    #pragma unroll
    for (int o = 16; o > 0; o >>= 1) s += __shfl_xor_sync(0xffffffffu, s, o);

    if (lane == 0) {
        const float an = s * g_rna[r] * g_rnp[j];
        const float term = fmaxf(1.0f + g_ap[r] - an, 0.f);
        atomicAdd(out, term * (1.0f / (float)B));
    }
}

extern "C" void kernel_launch(void* const* d_in, const int* in_sizes, int n_in,
                              void* d_out, int out_size)
{
    const float* anchor   = (const float*)d_in[0];
    const float* positive = (const float*)d_in[1];
    float* out = (float*)d_out;

    const int B = in_sizes[0] / EDIM;   // 8192

    cudaFuncSetAttribute(gemm_min_f16,
                         cudaFuncAttributeMaxDynamicSharedMemorySize, SMEM_DYN);

    normalize_kernel<<<B / 8, 256>>>(anchor, positive, out);
    dim3 grid(B / TN, B / TM);
    gemm_min_f16<<<grid, 256, SMEM_DYN>>>();
    an_term_kernel<<<B / 8, 256>>>(anchor, positive, out, B);
}